// round 2
// baseline (speedup 1.0000x reference)
#include <cuda_runtime.h>
#include <math.h>

#define BB 2
#define SS 4096
#define DD 2560
#define MS (BB*SS*DD)          // 20,971,520 elements per activation buffer
#define MM (BB*SS)             // 8192 rows
#define NC 16                  // scan chunks
#define CL (SS/NC)             // 256 per chunk

// ---------------- scratch (device globals; no allocation allowed) ----------
__device__ float g_Y[MS];      // gelu(x @ w_y^T + b_y)
__device__ float g_X[MS];      // x @ w_x^T + b_x
__device__ float g_C[MS];      // conv_out -> normalized_x -> h (in place)
__device__ float g_GX[MS];     // gate_x
__device__ float g_GA[MS];     // gate_a -> a (in place)
__device__ float g_chA[BB*NC*DD];
__device__ float g_chX[BB*NC*DD];
__device__ float g_Hs [BB*NC*DD];

#define ACT_NONE 0
#define ACT_GELU 1
#define ACT_SIG  2

// ---------------- generic fp32 NT GEMM: C = act(A(*A2) @ B^T + bias) -------
// A: [M x K] lda, B: [N x K] ldb, C: [M x N] ldc. Tiles 128x128x8, 256 thr.
// All of M,N divisible by 128 and K by 8 in this problem.
__global__ __launch_bounds__(256) void sgemm_nt(
    const float* __restrict__ A, const float* __restrict__ A2,
    const float* __restrict__ Bm, const float* __restrict__ bias,
    float* __restrict__ C,
    int K, int lda, int ldb, int ldc,
    long aOffZ, long bOffZ, long cOffZ, int act)
{
    __shared__ float As[8][132];
    __shared__ float Bs[8][132];

    long z = blockIdx.z;
    A  += z * aOffZ;
    Bm += z * bOffZ;
    C  += z * cOffZ;
    const float* A2z = A2 ? (A2 + z * aOffZ) : nullptr;

    const int m0 = blockIdx.y * 128;
    const int n0 = blockIdx.x * 128;
    const int tid = threadIdx.x;
    const int lrow = tid >> 1;          // 0..127
    const int lk   = (tid & 1) * 4;     // 0 or 4
    const int tx = tid & 15;            // 0..15 (cols)
    const int ty = tid >> 4;            // 0..15 (rows)

    float acc[8][8];
    #pragma unroll
    for (int i = 0; i < 8; i++)
        #pragma unroll
        for (int j = 0; j < 8; j++) acc[i][j] = 0.f;

    const float* Ap  = A  + (long)(m0 + lrow) * lda + lk;
    const float* A2p = A2z ? (A2z + (long)(m0 + lrow) * lda + lk) : nullptr;
    const float* Bp  = Bm + (long)(n0 + lrow) * ldb + lk;

    for (int k0 = 0; k0 < K; k0 += 8) {
        float4 av = *(const float4*)(Ap + k0);
        if (A2p) {
            float4 a2 = *(const float4*)(A2p + k0);
            av.x *= a2.x; av.y *= a2.y; av.z *= a2.z; av.w *= a2.w;
        }
        float4 bv = *(const float4*)(Bp + k0);
        As[lk+0][lrow] = av.x; As[lk+1][lrow] = av.y;
        As[lk+2][lrow] = av.z; As[lk+3][lrow] = av.w;
        Bs[lk+0][lrow] = bv.x; Bs[lk+1][lrow] = bv.y;
        Bs[lk+2][lrow] = bv.z; Bs[lk+3][lrow] = bv.w;
        __syncthreads();

        #pragma unroll
        for (int kk = 0; kk < 8; kk++) {
            float a[8], b[8];
            *(float4*)&a[0] = *(const float4*)&As[kk][ty*8];
            *(float4*)&a[4] = *(const float4*)&As[kk][ty*8+4];
            *(float4*)&b[0] = *(const float4*)&Bs[kk][tx*8];
            *(float4*)&b[4] = *(const float4*)&Bs[kk][tx*8+4];
            #pragma unroll
            for (int i = 0; i < 8; i++)
                #pragma unroll
                for (int j = 0; j < 8; j++)
                    acc[i][j] += a[i] * b[j];
        }
        __syncthreads();
    }

    #pragma unroll
    for (int i = 0; i < 8; i++) {
        long r = (long)(m0 + ty*8 + i) * ldc + n0 + tx*8;
        #pragma unroll
        for (int j = 0; j < 8; j++) {
            float v = acc[i][j] + bias[n0 + tx*8 + j];
            if (act == ACT_GELU) {
                float u = 0.7978845608028654f * (v + 0.044715f * v * v * v);
                v = 0.5f * v * (1.0f + tanhf(u));
            } else if (act == ACT_SIG) {
                v = 1.0f / (1.0f + expf(-v));
            }
            C[r + j] = v;
        }
    }
}

// ---------------- depthwise causal conv (W=4) ------------------------------
__global__ __launch_bounds__(512) void conv_k(
    const float* __restrict__ X,
    const float* __restrict__ cw,
    const float* __restrict__ cb,
    float* __restrict__ out)
{
    long i = (long)blockIdx.x * blockDim.x + threadIdx.x;
    if (i >= MS) return;
    int d = (int)(i % DD);
    int s = (int)((i / DD) % SS);
    float4 w = *(const float4*)(cw + d * 4);
    float v = cb[d];
    // k=0..3 maps to t = s-3+k
    if (s >= 3)      v += X[i - 3*DD] * w.x;
    if (s >= 2)      v += X[i - 2*DD] * w.y;
    if (s >= 1)      v += X[i - 1*DD] * w.z;
    v += X[i] * w.w;
    out[i] = v;
}

// ---------------- elementwise: a, normalized_x -----------------------------
// in: conv_out (Cb), gate_x (GX), gate_a (GA), a_param
// out (in place): GA <- a, Cb <- normalized_x
__global__ __launch_bounds__(512) void elem_k(
    float* __restrict__ Cb,
    const float* __restrict__ GX,
    float* __restrict__ GA,
    const float* __restrict__ a_param)
{
    long i = (long)blockIdx.x * blockDim.x + threadIdx.x;
    if (i >= MS) return;
    int d = (int)(i % DD);
    int s = (int)((i / DD) % SS);
    float ap = a_param[d];
    float sp = (ap > 20.f) ? ap : log1pf(expf(ap));     // softplus
    float la = -8.f * GA[i] * sp;
    float a  = expf(la);
    float mult = sqrtf(fmaxf(0.f, 1.f - expf(2.f * la)));
    if (s == 0) { a = 0.f; mult = 1.f; }
    float xn = Cb[i] * GX[i] * mult;
    GA[i] = a;
    Cb[i] = xn;
}

// ---------------- chunked linear scan: h_t = a_t h_{t-1} + x_t -------------
__global__ void scan1(const float* __restrict__ Ab,
                      const float* __restrict__ Xb,
                      float* __restrict__ chA, float* __restrict__ chX)
{
    int i = blockIdx.x * blockDim.x + threadIdx.x;   // < BB*NC*DD
    if (i >= BB*NC*DD) return;
    int d = i % DD;
    int c = (i / DD) % NC;
    int b = i / (DD * NC);
    long base = (long)b * SS * DD + (long)c * CL * DD + d;
    float Ap = 1.f, Xa = 0.f;
    for (int t = 0; t < CL; t++) {
        float a = Ab[base + (long)t * DD];
        float x = Xb[base + (long)t * DD];
        Ap = a * Ap;
        Xa = a * Xa + x;
    }
    chA[i] = Ap;
    chX[i] = Xa;
}

__global__ void scan2(const float* __restrict__ chA,
                      const float* __restrict__ chX,
                      const float* __restrict__ prev_h,
                      float* __restrict__ Hs)
{
    int i = blockIdx.x * blockDim.x + threadIdx.x;
    if (i >= BB*DD) return;
    int d = i % DD;
    int b = i / DD;
    float h = prev_h[i];
    for (int c = 0; c < NC; c++) {
        long j = (long)b * NC * DD + (long)c * DD + d;
        Hs[j] = h;
        h = chA[j] * h + chX[j];
    }
}

__global__ void scan3(const float* __restrict__ Ab,
                      float* __restrict__ Xb,       // in: x, out: h (in place)
                      const float* __restrict__ Hs)
{
    int i = blockIdx.x * blockDim.x + threadIdx.x;
    if (i >= BB*NC*DD) return;
    int d = i % DD;
    int c = (i / DD) % NC;
    int b = i / (DD * NC);
    long base = (long)b * SS * DD + (long)c * CL * DD + d;
    float h = Hs[i];
    for (int t = 0; t < CL; t++) {
        long j = base + (long)t * DD;
        h = Ab[j] * h + Xb[j];
        Xb[j] = h;
    }
}

// ---------------- launch ---------------------------------------------------
extern "C" void kernel_launch(void* const* d_in, const int* in_sizes, int n_in,
                              void* d_out, int out_size)
{
    const float* x_in   = (const float*)d_in[0];   // [B,S,H]
    // d_in[1] = position_ids (arange; reset <=> s==0, handled analytically)
    const float* prev_h = (const float*)d_in[2];   // [B,LRU]
    const float* w_y    = (const float*)d_in[3];
    const float* b_y    = (const float*)d_in[4];
    const float* w_x    = (const float*)d_in[5];
    const float* b_x    = (const float*)d_in[6];
    const float* w_out  = (const float*)d_in[7];
    const float* b_out  = (const float*)d_in[8];
    const float* conv_w = (const float*)d_in[9];
    const float* conv_b = (const float*)d_in[10];
    const float* a_prm  = (const float*)d_in[11];
    const float* ig_w   = (const float*)d_in[12];
    const float* ig_b   = (const float*)d_in[13];
    const float* ag_w   = (const float*)d_in[14];
    const float* ag_b   = (const float*)d_in[15];
    float* out = (float*)d_out;

    float *Y, *X, *C, *GX, *GA, *chA, *chX, *Hs;
    cudaGetSymbolAddress((void**)&Y,   g_Y);
    cudaGetSymbolAddress((void**)&X,   g_X);
    cudaGetSymbolAddress((void**)&C,   g_C);
    cudaGetSymbolAddress((void**)&GX,  g_GX);
    cudaGetSymbolAddress((void**)&GA,  g_GA);
    cudaGetSymbolAddress((void**)&chA, g_chA);
    cudaGetSymbolAddress((void**)&chX, g_chX);
    cudaGetSymbolAddress((void**)&Hs,  g_Hs);

    dim3 gBig(DD/128, MM/128, 1);       // 20 x 64
    dim3 gGate(256/128, MM/128, 10);    // 2 x 64 x 10

    // 1) y branch: gelu(x @ w_y^T + b_y)
    sgemm_nt<<<gBig, 256>>>(x_in, nullptr, w_y, b_y, Y,
                            DD, DD, DD, DD, 0, 0, 0, ACT_GELU);
    // 2) x branch linear
    sgemm_nt<<<gBig, 256>>>(x_in, nullptr, w_x, b_x, X,
                            DD, DD, DD, DD, 0, 0, 0, ACT_NONE);
    // 3) depthwise causal conv -> C
    conv_k<<<(MS + 511) / 512, 512>>>(X, conv_w, conv_b, C);
    // 4) block-diagonal gates (sigmoid): per-head 256x256 GEMMs
    sgemm_nt<<<gGate, 256>>>(C, nullptr, ig_w, ig_b, GX,
                             256, DD, 256, DD, 256, 65536, 256, ACT_SIG);
    sgemm_nt<<<gGate, 256>>>(C, nullptr, ag_w, ag_b, GA,
                             256, DD, 256, DD, 256, 65536, 256, ACT_SIG);
    // 5) elementwise: GA <- a, C <- normalized_x
    elem_k<<<(MS + 511) / 512, 512>>>(C, GX, GA, a_prm);
    // 6) chunked scan: C <- h
    scan1<<<(BB*NC*DD + 127) / 128, 128>>>(GA, C, chA, chX);
    scan2<<<(BB*DD + 127) / 128, 128>>>(chA, chX, prev_h, Hs);
    scan3<<<(BB*NC*DD + 127) / 128, 128>>>(GA, C, Hs);
    // 7) out = (h*y) @ w_out^T + b_out  (h*y fused into A-load)
    sgemm_nt<<<gBig, 256>>>(C, Y, w_out, b_out, out,
                            DD, DD, DD, DD, 0, 0, 0, ACT_NONE);
    (void)in_sizes; (void)n_in; (void)out_size;
}